// round 1
// baseline (speedup 1.0000x reference)
#include <cuda_runtime.h>
#include <cuda_bf16.h>
#include <stdint.h>

#define NPTS 256
#define DIM  256
#define KNN  16
#define EPSV 1e-12f

__device__ float g_Yn[NPTS * DIM];
__device__ float g_Ytn[NPTS * DIM];
__device__ float g_rn[NPTS];
__device__ float g_rt[NPTS];
__device__ float g_dself[NPTS];
__device__ float g_D1[NPTS * NPTS];
__device__ float g_D2[NPTS * NPTS];
__device__ float g_part[NPTS];

__device__ __forceinline__ float block_sum_256(float v, float* sh) {
    int lane = threadIdx.x & 31;
    int w    = threadIdx.x >> 5;
    #pragma unroll
    for (int o = 16; o; o >>= 1) v += __shfl_down_sync(0xffffffffu, v, o);
    if (lane == 0) sh[w] = v;
    __syncthreads();
    float r;
    if (w == 0) {
        r = (lane < 8) ? sh[lane] : 0.0f;
        #pragma unroll
        for (int o = 4; o; o >>= 1) r += __shfl_down_sync(0xffffffffu, r, o);
        if (lane == 0) sh[0] = r;
    }
    __syncthreads();
    r = sh[0];
    __syncthreads();
    return r;
}

// Kernel 1: per-row L2 normalize of yi and yi_t; store normalized rows,
// exact squared norms (s/(s+eps)), and the self distance 0.5*sqrt(||a-b||^2+eps).
__global__ void k_norm(const float* __restrict__ yi, const float* __restrict__ yit) {
    __shared__ float sh[8];
    int i = blockIdx.x;
    int t = threadIdx.x;
    float a = yi[i * DIM + t];
    float b = yit[i * DIM + t];
    float sa = block_sum_256(a * a, sh);
    float sb = block_sum_256(b * b, sh);
    float ia = 1.0f / sqrtf(sa + EPSV);
    float ib = 1.0f / sqrtf(sb + EPSV);
    float an = a * ia;
    float bn = b * ib;
    g_Yn[i * DIM + t]  = an;
    g_Ytn[i * DIM + t] = bn;
    float df = an - bn;
    float sd = block_sum_256(df * df, sh);
    if (t == 0) {
        g_rn[i] = sa * ia * ia;   // ||yn_i||^2 (== s/(s+eps), essentially 1)
        g_rt[i] = sb * ib * ib;
        g_dself[i] = 0.5f * sqrtf(sd + EPSV);
    }
}

// Kernel 2: dual Gram -> distance matrices.
// D1[i][j] = 0.5*sqrt(max(|yn_i|^2+|yn_j|^2-2<yn_i,yn_j>,0)+eps)
// D2[i][j] = same with ytn_i vs yn_j. B-tile (Yn rows for columns) is shared.
__global__ void k_dist() {
    __shared__ float As1[16][17];
    __shared__ float As2[16][17];
    __shared__ float Bs[16][17];
    int tx = threadIdx.x, ty = threadIdx.y;
    int row = blockIdx.y * 16 + ty;
    int col = blockIdx.x * 16 + tx;
    float acc1 = 0.0f, acc2 = 0.0f;
    for (int kk = 0; kk < DIM; kk += 16) {
        As1[ty][tx] = g_Yn[row * DIM + kk + tx];
        As2[ty][tx] = g_Ytn[row * DIM + kk + tx];
        Bs[ty][tx]  = g_Yn[(blockIdx.x * 16 + ty) * DIM + kk + tx];
        __syncthreads();
        #pragma unroll
        for (int k = 0; k < 16; k++) {
            float bval = Bs[tx][k];
            acc1 += As1[ty][k] * bval;
            acc2 += As2[ty][k] * bval;
        }
        __syncthreads();
    }
    float rnr = g_rn[row];
    float rnc = g_rn[col];
    float rtr = g_rt[row];
    float d1s = fmaxf(rnr + rnc - 2.0f * acc1, 0.0f) + EPSV;
    float d2s = fmaxf(rtr + rnc - 2.0f * acc2, 0.0f) + EPSV;
    g_D1[row * NPTS + col] = 0.5f * sqrtf(d1s);
    g_D2[row * NPTS + col] = 0.5f * sqrtf(d2s);
}

// Kernel 3: per row i, find the 16 smallest D1[i][j] (j != i) via 16 iterated
// block-wide argmin passes on packed (value_bits<<32 | index) keys.
// Lower index wins exact ties -> matches jax.lax.top_k ordering.
// Accumulate e1_i = sum_k (d1-d2)^2 - K*T, e2_i = relu(dself + 0.6 - nn1).
__global__ void k_select() {
    __shared__ float sd2[NPTS];
    __shared__ unsigned long long wsh[8];
    __shared__ unsigned long long winner;
    int i = blockIdx.x;
    int t = threadIdx.x;
    int lane = t & 31;
    int w    = t >> 5;

    float d1 = g_D1[i * NPTS + t];
    sd2[t]   = g_D2[i * NPTS + t];
    unsigned long long key =
        ((unsigned long long)__float_as_uint(d1) << 32) | (unsigned int)t;
    if (t == i) key = ~0ull;
    __syncthreads();

    float acc = 0.0f;
    float secnn = 0.0f;

    for (int it = 0; it < KNN; it++) {
        unsigned long long v = key;
        #pragma unroll
        for (int o = 16; o; o >>= 1) {
            unsigned long long u = __shfl_down_sync(0xffffffffu, v, o);
            v = (u < v) ? u : v;
        }
        if (lane == 0) wsh[w] = v;
        __syncthreads();
        if (w == 0) {
            unsigned long long v2 = (lane < 8) ? wsh[lane] : ~0ull;
            #pragma unroll
            for (int o = 4; o; o >>= 1) {
                unsigned long long u = __shfl_down_sync(0xffffffffu, v2, o);
                v2 = (u < v2) ? u : v2;
            }
            if (lane == 0) winner = v2;
        }
        __syncthreads();
        unsigned long long wv = winner;
        int jw = (int)(wv & 0xffffffffull);
        if (t == jw) key = ~0ull;  // remove winner from contention
        if (t == 0) {
            float d1w = __uint_as_float((unsigned int)(wv >> 32));
            float diff = d1w - sd2[jw];
            acc += diff * diff;
            if (it == 0) secnn = d1w;
        }
        __syncthreads();
    }

    if (t == 0) {
        float e1 = acc - (float)KNN * 0.0025f;
        float e2 = fmaxf(g_dself[i] + 0.6f - secnn, 0.0f);
        g_part[i] = e1 + e2;
    }
}

// Kernel 4: deterministic final reduction of 256 per-row partials.
__global__ void k_final(float* __restrict__ out) {
    __shared__ float sh[8];
    float v = g_part[threadIdx.x];
    float s = block_sum_256(v, sh);
    if (threadIdx.x == 0) out[0] = s;
}

extern "C" void kernel_launch(void* const* d_in, const int* in_sizes, int n_in,
                              void* d_out, int out_size) {
    const float* yi  = (const float*)d_in[0];
    const float* yit = (const float*)d_in[1];
    float* out = (float*)d_out;

    k_norm<<<NPTS, DIM>>>(yi, yit);
    k_dist<<<dim3(16, 16), dim3(16, 16)>>>();
    k_select<<<NPTS, NPTS>>>();
    k_final<<<1, NPTS>>>(out);
}